// round 5
// baseline (speedup 1.0000x reference)
#include <cuda_runtime.h>

// LoRALayerNorm: y = ((x - mean) * rsqrt(var + eps)) * scale + shift
// x [2,4096,8192] fp32 -> 8192 rows of N=8192. scale/shift = 2 * rank-4 diag.

#define N_FEAT 8192
#define RANK   4
#define TPB    512
#define V4T    (N_FEAT / 4 / TPB)   // 4 float4 per thread
#define NWARPS (TPB / 32)           // 16
#define EPS_LN 1e-5f

__device__ float g_scale[N_FEAT];
__device__ float g_shift[N_FEAT];

__global__ void compute_scales_kernel(const float* __restrict__ sA,
                                      const float* __restrict__ sB,
                                      const float* __restrict__ hA,
                                      const float* __restrict__ hB) {
    int i = blockIdx.x * blockDim.x + threadIdx.x;
    if (i < N_FEAT) {
        float s = 0.f, h = 0.f;
#pragma unroll
        for (int r = 0; r < RANK; r++) {
            s = fmaf(sA[i * RANK + r], sB[r * N_FEAT + i], s);
            h = fmaf(hA[i * RANK + r], hB[r * N_FEAT + i], h);
        }
        g_scale[i] = s * 2.0f;   // SCALING = ALPHA/RANK = 8/4
        g_shift[i] = h * 2.0f;
    }
}

__global__ __launch_bounds__(TPB, 2)
void lora_ln_kernel(const float* __restrict__ x,
                    float* __restrict__ out,
                    int rows) {
    extern __shared__ float4 smem4[];                 // 64 KB: scale + shift
    float4* s_scale = smem4;
    float4* s_shift = smem4 + N_FEAT / 4;
    __shared__ float  red[2][2 * NWARPS];             // parity double-buffered
    __shared__ float2 s_stats[2];

    const float4* gsc4 = reinterpret_cast<const float4*>(g_scale);
    const float4* gsh4 = reinterpret_cast<const float4*>(g_shift);
    for (int i = threadIdx.x; i < N_FEAT / 4; i += TPB) {
        s_scale[i] = gsc4[i];
        s_shift[i] = gsh4[i];
    }
    __syncthreads();

    const int lane = threadIdx.x & 31;
    const int warp = threadIdx.x >> 5;
    const float invN = 1.0f / (float)N_FEAT;

    int row = blockIdx.x;
    if (row >= rows) return;

    // Prologue: load first row.
    float4 v[V4T];
    {
        const float4* xr = reinterpret_cast<const float4*>(x + (size_t)row * N_FEAT);
#pragma unroll
        for (int j = 0; j < V4T; j++)
            v[j] = __ldcs(&xr[threadIdx.x + j * TPB]);
    }

    int par = 0;
    for (; row < rows; row += gridDim.x, par ^= 1) {
        // Local accumulation (consumes v -> v free for next prefetch... but we
        // still need v for the store, so prefetch goes into p[]).
        float sum = 0.f, sq = 0.f;
#pragma unroll
        for (int j = 0; j < V4T; j++) {
            sum += v[j].x + v[j].y + v[j].z + v[j].w;
            sq = fmaf(v[j].x, v[j].x, sq);
            sq = fmaf(v[j].y, v[j].y, sq);
            sq = fmaf(v[j].z, v[j].z, sq);
            sq = fmaf(v[j].w, v[j].w, sq);
        }

        // Prefetch next row NOW, so the LDGs are in flight across the
        // reduction barriers and the store phase.
        const int nrow = row + gridDim.x;
        float4 p[V4T];
        if (nrow < rows) {
            const float4* xn = reinterpret_cast<const float4*>(x + (size_t)nrow * N_FEAT);
#pragma unroll
            for (int j = 0; j < V4T; j++)
                p[j] = __ldcs(&xn[threadIdx.x + j * TPB]);
        }

        // Warp reduction.
#pragma unroll
        for (int o = 16; o > 0; o >>= 1) {
            sum += __shfl_xor_sync(0xFFFFFFFFu, sum, o);
            sq  += __shfl_xor_sync(0xFFFFFFFFu, sq, o);
        }
        if (lane == 0) { red[par][2 * warp] = sum; red[par][2 * warp + 1] = sq; }
        __syncthreads();

        // Block reduction (warp 0 over 16 partials).
        if (warp == 0) {
            float a = (lane < NWARPS) ? red[par][2 * lane]     : 0.f;
            float b = (lane < NWARPS) ? red[par][2 * lane + 1] : 0.f;
#pragma unroll
            for (int o = NWARPS / 2; o > 0; o >>= 1) {
                a += __shfl_xor_sync(0xFFFFFFFFu, a, o);
                b += __shfl_xor_sync(0xFFFFFFFFu, b, o);
            }
            if (lane == 0) {
                float mean = a * invN;
                float var  = fmaf(-mean, mean, b * invN);
                s_stats[par] = make_float2(mean, rsqrtf(var + EPS_LN));
            }
        }
        __syncthreads();

        const float mean = s_stats[par].x;
        const float rstd = s_stats[par].y;

        // Normalize + affine + streaming store.
        float4* orw = reinterpret_cast<float4*>(out + (size_t)row * N_FEAT);
#pragma unroll
        for (int j = 0; j < V4T; j++) {
            const int i4 = threadIdx.x + j * TPB;
            float4 sc = s_scale[i4];
            float4 sh = s_shift[i4];
            float4 o;
            o.x = fmaf((v[j].x - mean) * rstd, sc.x, sh.x);
            o.y = fmaf((v[j].y - mean) * rstd, sc.y, sh.y);
            o.z = fmaf((v[j].z - mean) * rstd, sc.z, sh.z);
            o.w = fmaf((v[j].w - mean) * rstd, sc.w, sh.w);
            __stcs(&orw[i4], o);
        }

        // Rotate prefetch buffer in (waits on the in-flight loads only here).
        if (nrow < rows) {
#pragma unroll
            for (int j = 0; j < V4T; j++) v[j] = p[j];
        }
        // No trailing barrier: next iteration uses the other red[]/s_stats parity.
    }
}

extern "C" void kernel_launch(void* const* d_in, const int* in_sizes, int n_in,
                              void* d_out, int out_size) {
    const float* x  = (const float*)d_in[0];
    const float* sA = (const float*)d_in[1];
    const float* sB = (const float*)d_in[2];
    const float* hA = (const float*)d_in[3];
    const float* hB = (const float*)d_in[4];
    float* out = (float*)d_out;

    const int rows = in_sizes[0] / N_FEAT;           // 8192

    compute_scales_kernel<<<(N_FEAT + 255) / 256, 256>>>(sA, sB, hA, hB);

    const int smem_bytes = 2 * N_FEAT * sizeof(float);   // 64 KB dynamic
    cudaFuncSetAttribute(lora_ln_kernel,
                         cudaFuncAttributeMaxDynamicSharedMemorySize, smem_bytes);

    int grid = 148 * 2;                                  // one wave, 2 CTAs/SM
    if (grid > rows) grid = rows;
    lora_ln_kernel<<<grid, TPB, smem_bytes>>>(x, out, rows);
}